// round 15
// baseline (speedup 1.0000x reference)
#include <cuda_runtime.h>
#include <cuda_fp16.h>
#include <math.h>
#include <stdint.h>

// Problem dims
#define T_   4
#define B_   16
#define NN_  1024
#define C_   512
#define H_   8
#define D_   64
#define M_   65536        // T*B*N
#define BNC_ 8388608      // B*N*C
#define RPT_ 16384        // rows per T step (B*N)

// Scratch (device globals; no allocation allowed)
__device__ __half g_xs[(size_t)M_ * C_];
__device__ __half g_q [(size_t)M_ * C_];
__device__ __half g_k [(size_t)M_ * C_];
__device__ __half g_v [(size_t)M_ * C_];
__device__ float  g_kvpart[(size_t)T_ * B_ * 8 * C_];
__device__ __half g_kvs[(size_t)T_ * B_ * C_];
// Split weights: 4 matrices x hi/mid fp16 planes (mid scaled by 2^12)
__device__ __half g_Wh[4 * C_ * C_];
__device__ __half g_Wm[4 * C_ * C_];

// ---------------------------------------------------------------------------
// 0) split weights: w = hi + mid*2^-12, both fp16 (residual <= 2^-24 |w|)
// ---------------------------------------------------------------------------
__global__ void prep_split_kernel(const float* __restrict__ Wq,
                                  const float* __restrict__ Wk,
                                  const float* __restrict__ Wv,
                                  const float* __restrict__ Wp) {
    int i = blockIdx.x * blockDim.x + threadIdx.x;
    int mat = i >> 18;
    int r = i & 262143;
    const float* src = (mat == 0) ? Wq : (mat == 1) ? Wk : (mat == 2) ? Wv : Wp;
    float w = src[r];
    __half h = __float2half_rn(w);
    float r1 = w - __half2float(h);
    g_Wh[i] = h;
    g_Wm[i] = __float2half_rn(r1 * 4096.0f);   // scaled into normal range
}

// ---------------------------------------------------------------------------
// 1) shortcut LIF on x -> binary xs (fp16), float4-vectorized
// ---------------------------------------------------------------------------
__global__ void lif_x_kernel(const float* __restrict__ x) {
    size_t i4 = (size_t)blockIdx.x * blockDim.x + threadIdx.x;
    const float4* x4 = (const float4*)x;
    uint2* dst = (uint2*)g_xs;
    float v0 = 0.f, v1 = 0.f, v2 = 0.f, v3 = 0.f;
#pragma unroll
    for (int t = 0; t < T_; ++t) {
        float4 xv = x4[(size_t)t * (BNC_ / 4) + i4];
        v0 = v0 + (xv.x - v0) * 0.5f;
        v1 = v1 + (xv.y - v1) * 0.5f;
        v2 = v2 + (xv.z - v2) * 0.5f;
        v3 = v3 + (xv.w - v3) * 0.5f;
        bool s0 = v0 >= 1.f, s1 = v1 >= 1.f, s2 = v2 >= 1.f, s3 = v3 >= 1.f;
        __half2 lo = __floats2half2_rn(s0 ? 1.f : 0.f, s1 ? 1.f : 0.f);
        __half2 hi = __floats2half2_rn(s2 ? 1.f : 0.f, s3 ? 1.f : 0.f);
        uint2 o;
        o.x = *(uint32_t*)&lo;
        o.y = *(uint32_t*)&hi;
        dst[(size_t)t * (BNC_ / 4) + i4] = o;
        if (s0) v0 = 0.f;
        if (s1) v1 = 0.f;
        if (s2) v2 = 0.f;
        if (s3) v3 = 0.f;
    }
}

// ---------------------------------------------------------------------------
// Tensor-core GEMM: CTA 128x64, BK=64 (8 chunks), 2-stage cp.async ring,
// fp16 2-plane weights, per-plane fp32 accumulators, fold c = hi + 2^-12*mid,
// B fragments via ldmatrix.x4.trans.
// MODE 0 (QKV, FUSED BN+LIF): grid over (bn-block, 1536 cols); t-loop inside
//   the CTA; LIF membrane state in 32KB smem (one element per thread-slot);
//   writes binary q/k/v spikes (+ transposed v into d_out) directly. No g_y.
// MODE 1 (P): A = g_q, kv mask on A fragments, epilogue bias+BN+identity.
// ---------------------------------------------------------------------------
#define PA 72   // A smem pitch (fp16); 144B rows, conflict-free
#define PB 72   // B smem pitch; 144B
#define ASTG (128 * PA * 2)          // 18432 B per A stage
#define BSTG (2 * 64 * PB * 2)       // 18432 B per B stage
#define RING_BYTES (2 * (ASTG + BSTG))        // 73728
#define STATE_BYTES (128 * 64 * 4)            // 32768 (MODE 0 only)
#define SM_TOTAL0 (RING_BYTES + STATE_BYTES)  // 106496
#define SM_TOTAL1 RING_BYTES

__device__ __forceinline__ uint32_t smem_u32(const void* p) {
    uint32_t a;
    asm("{ .reg .u64 t; cvta.to.shared.u64 t, %1; cvt.u32.u64 %0, t; }" : "=r"(a) : "l"(p));
    return a;
}
__device__ __forceinline__ void mma16816(float* c, const uint32_t* a, const uint32_t* b) {
    asm volatile(
        "mma.sync.aligned.m16n8k16.row.col.f32.f16.f16.f32 "
        "{%0,%1,%2,%3}, {%4,%5,%6,%7}, {%8,%9}, {%0,%1,%2,%3};"
        : "+f"(c[0]), "+f"(c[1]), "+f"(c[2]), "+f"(c[3])
        : "r"(a[0]), "r"(a[1]), "r"(a[2]), "r"(a[3]), "r"(b[0]), "r"(b[1]));
}
__device__ __forceinline__ void cpasync16(uint32_t dst, const void* src) {
    asm volatile("cp.async.cg.shared.global [%0], [%1], 16;" :: "r"(dst), "l"(src));
}
__device__ __forceinline__ void hmul2u(uint32_t& r, uint32_t m) {
    __half2 t = __hmul2(*(__half2*)&r, *(__half2*)&m);
    r = *(uint32_t*)&t;
}

template <int MODE>
__global__ void __launch_bounds__(256, 2)
gemm_tc_kernel(const float* __restrict__ bq,
               const float* __restrict__ bk,
               const float* __restrict__ bnq,
               const float* __restrict__ bnk,
               const float* __restrict__ bnv,
               float* __restrict__ vout,
               const float* __restrict__ bp,
               const float* __restrict__ bnp,
               const float* __restrict__ x,
               float* __restrict__ outp) {
    extern __shared__ __align__(16) char dynsmem[];
    const uint32_t sAs = smem_u32(dynsmem);
    const uint32_t sBs = sAs + 2 * ASTG;
    float* stf = (float*)(dynsmem + RING_BYTES);   // MODE 0 LIF state

    const int m0 = blockIdx.x * 128;
    const int n0 = blockIdx.y * 64;
    const int wsel = (MODE == 0) ? (n0 >> 9) : 3;
    const int nl0 = (MODE == 0) ? (n0 & 511) : n0;
    const __half* Wh = &g_Wh[(size_t)wsel * C_ * C_];
    const __half* Wm = &g_Wm[(size_t)wsel * C_ * C_];

    const int tid = threadIdx.x;
    const int lane = tid & 31;
    const int warp = tid >> 5;
    const int wm = warp & 3;          // 4 warps along M (32 rows each)
    const int wn = warp >> 2;         // 2 warps along N (32 cols each)

    const uint32_t aBase = sAs + (uint32_t)(((wm * 32 + (lane & 15)) * PA + (lane >> 4) * 8) * 2);
    const uint32_t bBase4 = sBs + (uint32_t)((
        (((lane >> 3) & 1) * 8 + (lane & 7)) * PB +
        wn * 32 + (lane >> 4) * 8) * 2);

    const int tb = m0 >> 10;
    const __half2* kvp = (const __half2*)&g_kvs[(size_t)tb * C_];

    const float* bnP = (MODE == 0)
        ? ((wsel == 0) ? bnq : (wsel == 1) ? bnk : bnv) : bnp;
    __half* spkdst = (wsel == 0) ? g_q : (wsel == 1) ? g_k : g_v;

    const int TSTEPS = (MODE == 0) ? 4 : 1;
    for (int t = 0; t < TSTEPS; ++t) {
        const __half* Abase = (MODE == 0)
            ? &g_xs[((size_t)t * RPT_ + m0) * C_]
            : &g_q[(size_t)m0 * C_];

        auto load_tiles = [&](int k0, int stg) {
#pragma unroll
            for (int i = 0; i < 4; ++i) {
                int idx = i * 256 + tid;
                int row = idx >> 3;
                int kc8 = (idx & 7) * 8;
                uint32_t dst = sAs + (uint32_t)(stg * ASTG + (row * PA + kc8) * 2);
                cpasync16(dst, Abase + (size_t)row * C_ + k0 + kc8);
            }
#pragma unroll
            for (int j = 0; j < 4; ++j) {
                int idx = j * 256 + tid;
                int plane = idx >> 9;
                int rem = idx & 511;
                int kr = rem >> 3;
                int nc = (rem & 7) * 8;
                const __half* src = (plane == 0) ? Wh : Wm;
                uint32_t dst = sBs + (uint32_t)(stg * BSTG + ((plane * 64 + kr) * PB + nc) * 2);
                cpasync16(dst, src + (size_t)(k0 + kr) * C_ + nl0 + nc);
            }
        };

        float acc[2][2][4][4] = {};   // [plane][mt][nt][4]
        load_tiles(0, 0);
        asm volatile("cp.async.commit_group;");
        int buf = 0;

        for (int kc = 0; kc < 8; ++kc) {
            asm volatile("cp.async.wait_group 0;");
            __syncthreads();
            if (kc < 7) {
                load_tiles((kc + 1) * 64, buf ^ 1);
                asm volatile("cp.async.commit_group;");
            }
            const int k0 = kc * 64;
#pragma unroll
            for (int ks = 0; ks < 4; ++ks) {
                uint32_t a[2][4];
#pragma unroll
                for (int mt = 0; mt < 2; ++mt) {
                    uint32_t addr = aBase + (uint32_t)(buf * ASTG + (mt * 16 * PA + ks * 16) * 2);
                    asm volatile(
                        "ldmatrix.sync.aligned.m8n8.x4.shared.b16 {%0,%1,%2,%3}, [%4];"
                        : "=r"(a[mt][0]), "=r"(a[mt][1]), "=r"(a[mt][2]), "=r"(a[mt][3])
                        : "r"(addr));
                }
                if (MODE == 1) {
                    int kb = (k0 >> 1) + ks * 8 + (lane & 3);
                    uint32_t kl = *(const uint32_t*)&kvp[kb];
                    uint32_t kh = *(const uint32_t*)&kvp[kb + 4];
#pragma unroll
                    for (int mt = 0; mt < 2; ++mt) {
                        hmul2u(a[mt][0], kl);
                        hmul2u(a[mt][1], kl);
                        hmul2u(a[mt][2], kh);
                        hmul2u(a[mt][3], kh);
                    }
                }
#pragma unroll
                for (int plane = 0; plane < 2; ++plane) {
                    uint32_t b[4][2];
#pragma unroll
                    for (int ntp = 0; ntp < 2; ++ntp) {
                        uint32_t addr = bBase4 + (uint32_t)(buf * BSTG +
                            ((plane * 64 + ks * 16) * PB + ntp * 16) * 2);
                        asm volatile(
                            "ldmatrix.sync.aligned.m8n8.x4.trans.shared.b16 {%0,%1,%2,%3}, [%4];"
                            : "=r"(b[2 * ntp][0]), "=r"(b[2 * ntp][1]),
                              "=r"(b[2 * ntp + 1][0]), "=r"(b[2 * ntp + 1][1])
                            : "r"(addr));
                    }
#pragma unroll
                    for (int mt = 0; mt < 2; ++mt)
#pragma unroll
                        for (int nt = 0; nt < 4; ++nt)
                            mma16816(acc[plane][mt][nt], a[mt], b[nt]);
                }
            }
            buf ^= 1;
        }

        // ---- epilogue ----
#pragma unroll
        for (int mt = 0; mt < 2; ++mt) {
#pragma unroll
            for (int nt = 0; nt < 4; ++nt) {
#pragma unroll
                for (int half = 0; half < 2; ++half) {
                    int rloc = wm * 32 + mt * 16 + (lane >> 2) + half * 8;
                    int col0 = wn * 32 + nt * 8 + (lane & 3) * 2;
                    float c0 = fmaf(acc[1][mt][nt][half * 2 + 0], 0x1p-12f,
                                    acc[0][mt][nt][half * 2 + 0]);
                    float c1 = fmaf(acc[1][mt][nt][half * 2 + 1], 0x1p-12f,
                                    acc[0][mt][nt][half * 2 + 1]);
                    if (MODE == 0) {
                        int brow = m0 + rloc;              // bn_i
                        int lc = nl0 + col0;               // local channel in matrix
                        int sidx = rloc * 64 + col0;
                        float sf[2];
#pragma unroll
                        for (int e = 0; e < 2; ++e) {
                            int cc = lc + e;
                            float bias = (wsel == 0) ? bq[cc] : (wsel == 1) ? bk[cc] : 0.f;
                            float gamma = bnP[cc], beta = bnP[512 + cc];
                            float mean = bnP[1024 + cc], var = bnP[1536 + cc];
                            float rinv = 1.0f / sqrtf(var + 1e-5f);
                            float y = (e == 0 ? c0 : c1) + bias;
                            float u = __fadd_rn(__fmul_rn(__fmul_rn(gamma, __fadd_rn(y, -mean)), rinv), beta);
                            float v = (t == 0) ? 0.f : stf[sidx + e];
                            v = v + (u - v) * 0.5f;
                            bool s = (v >= 1.0f);
                            sf[e] = s ? 1.f : 0.f;
                            stf[sidx + e] = s ? 0.f : v;
                        }
                        __half2 pk = __floats2half2_rn(sf[0], sf[1]);
                        *(__half2*)&spkdst[(size_t)t * BNC_ + (size_t)brow * C_ + lc] = pk;
                        if (wsel == 2) {
                            int b = brow >> 10, n = brow & 1023, h = lc >> 6, d = lc & 63;
                            *(float2*)&vout[((((size_t)t * B_ + b) * H_ + h) * NN_ + n) * D_ + d] =
                                make_float2(sf[0], sf[1]);
                        }
                    } else {
                        int row = m0 + rloc;
                        int c = n0 + col0;
                        float2 o;
#pragma unroll
                        for (int e = 0; e < 2; ++e) {
                            int cc = c + e;
                            float gamma = bnp[cc], beta = bnp[512 + cc];
                            float mean = bnp[1024 + cc], var = bnp[1536 + cc];
                            float rinv = 1.0f / sqrtf(var + 1e-5f);
                            float yv = (e == 0 ? c0 : c1) + bp[cc];
                            float u = __fadd_rn(__fmul_rn(__fmul_rn(gamma, __fadd_rn(yv, -mean)), rinv), beta);
                            float r = u + x[(size_t)row * C_ + cc];
                            if (e == 0) o.x = r; else o.y = r;
                        }
                        *(float2*)&outp[(size_t)row * C_ + c] = o;
                    }
                }
            }
        }
        if (MODE == 0 && t < 3) __syncthreads();
    }
}

// ---------------------------------------------------------------------------
// 4) kv = sum_n k*v (exact binary sums), half2-vectorized; then LIF(0.5)
// ---------------------------------------------------------------------------
__global__ void kv_partial_kernel() {
    int blk = blockIdx.x;
    int chunk = blk & 7;
    int tb = blk >> 3;
    int c2 = threadIdx.x;
    const __half2* k2 = (const __half2*)&g_k[(size_t)tb * NN_ * C_ + (size_t)chunk * 128 * C_];
    const __half2* v2 = (const __half2*)&g_v[(size_t)tb * NN_ * C_ + (size_t)chunk * 128 * C_];
    float sx = 0.f, sy = 0.f;
    for (int n = 0; n < 128; ++n) {
        __half2 p = __hmul2(k2[n * 256 + c2], v2[n * 256 + c2]);
        float2 pf = __half22float2(p);
        sx += pf.x;
        sy += pf.y;
    }
    g_kvpart[(size_t)blk * C_ + 2 * c2]     = sx;
    g_kvpart[(size_t)blk * C_ + 2 * c2 + 1] = sy;
}

__global__ void kv_lif_kernel() {
    int idx = blockIdx.x * blockDim.x + threadIdx.x;
    int b = idx >> 9, c = idx & 511;
    float v = 0.f;
#pragma unroll
    for (int t = 0; t < T_; ++t) {
        int tb = t * B_ + b;
        float s = 0.f;
#pragma unroll
        for (int ch = 0; ch < 8; ++ch)
            s += g_kvpart[((size_t)tb * 8 + ch) * C_ + c];
        v = v + (s - v) * 0.5f;
        bool sp = (v >= 0.5f);
        g_kvs[(size_t)tb * C_ + c] = sp ? __float2half(1.f) : __float2half(0.f);
        if (sp) v = 0.f;
    }
}

// ---------------------------------------------------------------------------
extern "C" void kernel_launch(void* const* d_in, const int* in_sizes, int n_in,
                              void* d_out, int out_size) {
    const float* x   = (const float*)d_in[0];
    const float* Wq  = (const float*)d_in[1];
    const float* bq  = (const float*)d_in[2];
    const float* Wk  = (const float*)d_in[3];
    const float* bk  = (const float*)d_in[4];
    const float* Wv  = (const float*)d_in[5];
    const float* Wp  = (const float*)d_in[6];
    const float* bp  = (const float*)d_in[7];
    const float* bnq = (const float*)d_in[8];
    const float* bnk = (const float*)d_in[9];
    const float* bnv = (const float*)d_in[10];
    const float* bnp = (const float*)d_in[11];
    float* out  = (float*)d_out;
    float* vout = out + (size_t)M_ * C_;   // tuple output: (out, v) concatenated

    cudaFuncSetAttribute((const void*)gemm_tc_kernel<0>,
                         cudaFuncAttributeMaxDynamicSharedMemorySize, SM_TOTAL0);
    cudaFuncSetAttribute((const void*)gemm_tc_kernel<1>,
                         cudaFuncAttributeMaxDynamicSharedMemorySize, SM_TOTAL1);

    prep_split_kernel<<<4096, 256>>>(Wq, Wk, Wv, Wp);
    lif_x_kernel<<<BNC_ / 4 / 256, 256>>>(x);

    dim3 gq(RPT_ / 128, 1536 / 64);   // (128, 24) — t-loop inside CTA
    gemm_tc_kernel<0><<<gq, 256, SM_TOTAL0>>>(bq, bk, bnq, bnk, bnv, vout,
                                              nullptr, nullptr, nullptr, nullptr);

    kv_partial_kernel<<<T_ * B_ * 8, 256>>>();
    kv_lif_kernel<<<(B_ * C_) / 256, 256>>>();

    dim3 gp(M_ / 128, C_ / 64);       // (512, 8)
    gemm_tc_kernel<1><<<gp, 256, SM_TOTAL1>>>(nullptr, nullptr, nullptr, nullptr, nullptr, nullptr,
                                              bp, bnp, x, out);
}

// round 16
// speedup vs baseline: 1.1161x; 1.1161x over previous
#include <cuda_runtime.h>
#include <cuda_fp16.h>
#include <math.h>
#include <stdint.h>

// Problem dims
#define T_   4
#define B_   16
#define NN_  1024
#define C_   512
#define H_   8
#define D_   64
#define M_   65536        // T*B*N
#define BNC_ 8388608      // B*N*C
#define RPT_ 16384        // rows per T step (B*N)
#define QC_  1536         // fused QKV output columns

// Scratch (device globals; no allocation allowed)
__device__ __half g_xs[(size_t)M_ * C_];
__device__ float  g_y [(size_t)M_ * QC_];
__device__ __half g_q [(size_t)M_ * C_];
__device__ __half g_k [(size_t)M_ * C_];
__device__ __half g_v [(size_t)M_ * C_];
__device__ float  g_kvpart[(size_t)T_ * B_ * 8 * C_];
__device__ __half g_kvs[(size_t)T_ * B_ * C_];
// Split weights: 4 matrices x hi/mid fp16 planes (mid scaled by 2^12)
__device__ __half g_Wh[4 * C_ * C_];
__device__ __half g_Wm[4 * C_ * C_];

// ---------------------------------------------------------------------------
// 0) split weights: w = hi + mid*2^-12, both fp16 (residual <= 2^-24 |w|)
// ---------------------------------------------------------------------------
__global__ void prep_split_kernel(const float* __restrict__ Wq,
                                  const float* __restrict__ Wk,
                                  const float* __restrict__ Wv,
                                  const float* __restrict__ Wp) {
    int i = blockIdx.x * blockDim.x + threadIdx.x;
    int mat = i >> 18;
    int r = i & 262143;
    const float* src = (mat == 0) ? Wq : (mat == 1) ? Wk : (mat == 2) ? Wv : Wp;
    float w = src[r];
    __half h = __float2half_rn(w);
    float r1 = w - __half2float(h);
    g_Wh[i] = h;
    g_Wm[i] = __float2half_rn(r1 * 4096.0f);   // scaled into normal range
}

// ---------------------------------------------------------------------------
// 1) shortcut LIF on x -> binary xs (fp16), float4-vectorized
// ---------------------------------------------------------------------------
__global__ void lif_x_kernel(const float* __restrict__ x) {
    size_t i4 = (size_t)blockIdx.x * blockDim.x + threadIdx.x;
    const float4* x4 = (const float4*)x;
    uint2* dst = (uint2*)g_xs;
    float v0 = 0.f, v1 = 0.f, v2 = 0.f, v3 = 0.f;
#pragma unroll
    for (int t = 0; t < T_; ++t) {
        float4 xv = x4[(size_t)t * (BNC_ / 4) + i4];
        v0 = v0 + (xv.x - v0) * 0.5f;
        v1 = v1 + (xv.y - v1) * 0.5f;
        v2 = v2 + (xv.z - v2) * 0.5f;
        v3 = v3 + (xv.w - v3) * 0.5f;
        bool s0 = v0 >= 1.f, s1 = v1 >= 1.f, s2 = v2 >= 1.f, s3 = v3 >= 1.f;
        __half2 lo = __floats2half2_rn(s0 ? 1.f : 0.f, s1 ? 1.f : 0.f);
        __half2 hi = __floats2half2_rn(s2 ? 1.f : 0.f, s3 ? 1.f : 0.f);
        uint2 o;
        o.x = *(uint32_t*)&lo;
        o.y = *(uint32_t*)&hi;
        dst[(size_t)t * (BNC_ / 4) + i4] = o;
        if (s0) v0 = 0.f;
        if (s1) v1 = 0.f;
        if (s2) v2 = 0.f;
        if (s3) v3 = 0.f;
    }
}

// ---------------------------------------------------------------------------
// Tensor-core GEMM: CTA 128x64, BK=64 (8 chunks), 2-stage cp.async ring.
// B fragments via ldmatrix.x4.trans.
// MODE 0 (QKV): fp16 2-plane weights (hi+mid), per-plane fp32 accumulators,
//               fold c = hi + 2^-12*mid. +bias, write g_y fp32.
// MODE 1 (P):   fp16 HI PLANE ONLY (final out tolerance 1e-3 >> 2^-12 error);
//               half the mma work. kv mask on A fragments,
//               epilogue bias+BN+identity.
// ---------------------------------------------------------------------------
#define PA 72   // A smem pitch (fp16); 144B rows, conflict-free
#define PB 72   // B smem pitch; 144B
#define ASTG (128 * PA * 2)          // 18432 B per A stage
#define BSTG (2 * 64 * PB * 2)       // 18432 B per B stage (2-plane layout kept)
#define SM_TOTAL (2 * (ASTG + BSTG)) // 73728 B dynamic smem

__device__ __forceinline__ uint32_t smem_u32(const void* p) {
    uint32_t a;
    asm("{ .reg .u64 t; cvta.to.shared.u64 t, %1; cvt.u32.u64 %0, t; }" : "=r"(a) : "l"(p));
    return a;
}
__device__ __forceinline__ void mma16816(float* c, const uint32_t* a, const uint32_t* b) {
    asm volatile(
        "mma.sync.aligned.m16n8k16.row.col.f32.f16.f16.f32 "
        "{%0,%1,%2,%3}, {%4,%5,%6,%7}, {%8,%9}, {%0,%1,%2,%3};"
        : "+f"(c[0]), "+f"(c[1]), "+f"(c[2]), "+f"(c[3])
        : "r"(a[0]), "r"(a[1]), "r"(a[2]), "r"(a[3]), "r"(b[0]), "r"(b[1]));
}
__device__ __forceinline__ void cpasync16(uint32_t dst, const void* src) {
    asm volatile("cp.async.cg.shared.global [%0], [%1], 16;" :: "r"(dst), "l"(src));
}
__device__ __forceinline__ void hmul2u(uint32_t& r, uint32_t m) {
    __half2 t = __hmul2(*(__half2*)&r, *(__half2*)&m);
    r = *(uint32_t*)&t;
}

template <int MODE>
__global__ void __launch_bounds__(256, 2)
gemm_tc_kernel(const float* __restrict__ bq,
               const float* __restrict__ bk,
               const float* __restrict__ bp,
               const float* __restrict__ bnp,
               const float* __restrict__ x,
               float* __restrict__ outp) {
    extern __shared__ __align__(16) char dynsmem[];
    const uint32_t sAs = smem_u32(dynsmem);
    const uint32_t sBs = sAs + 2 * ASTG;

    constexpr int NPLANES = (MODE == 0) ? 2 : 1;

    const int m0 = blockIdx.x * 128;
    const int n0 = blockIdx.y * 64;
    const int wsel = (MODE == 0) ? (n0 >> 9) : 3;
    const int nl0 = (MODE == 0) ? (n0 & 511) : n0;
    const __half* Wh = &g_Wh[(size_t)wsel * C_ * C_];
    const __half* Wm = &g_Wm[(size_t)wsel * C_ * C_];

    const int tid = threadIdx.x;
    const int lane = tid & 31;
    const int warp = tid >> 5;
    const int wm = warp & 3;          // 4 warps along M (32 rows each)
    const int wn = warp >> 2;         // 2 warps along N (32 cols each)

    const uint32_t aBase = sAs + (uint32_t)(((wm * 32 + (lane & 15)) * PA + (lane >> 4) * 8) * 2);
    const uint32_t bBase4 = sBs + (uint32_t)((
        (((lane >> 3) & 1) * 8 + (lane & 7)) * PB +
        wn * 32 + (lane >> 4) * 8) * 2);

    const __half* Abase = (MODE == 0) ? &g_xs[(size_t)m0 * C_]
                                      : &g_q[(size_t)m0 * C_];
    const int tb = m0 >> 10;
    const __half2* kvp = (const __half2*)&g_kvs[(size_t)tb * C_];

    auto load_tiles = [&](int k0, int stg) {
        // A: 128 rows x 64 cols fp16 = 1024 x 16B
#pragma unroll
        for (int i = 0; i < 4; ++i) {
            int idx = i * 256 + tid;
            int row = idx >> 3;
            int kc8 = (idx & 7) * 8;
            uint32_t dst = sAs + (uint32_t)(stg * ASTG + (row * PA + kc8) * 2);
            cpasync16(dst, Abase + (size_t)row * C_ + k0 + kc8);
        }
        // B: NPLANES x 64 k-rows x 64 n
#pragma unroll
        for (int j = 0; j < 2 * NPLANES; ++j) {
            int idx = j * 256 + tid;
            int plane = idx >> 9;
            int rem = idx & 511;
            int kr = rem >> 3;
            int nc = (rem & 7) * 8;
            const __half* src = (plane == 0) ? Wh : Wm;
            uint32_t dst = sBs + (uint32_t)(stg * BSTG + ((plane * 64 + kr) * PB + nc) * 2);
            cpasync16(dst, src + (size_t)(k0 + kr) * C_ + nl0 + nc);
        }
    };

    float acc[NPLANES][2][4][4] = {};   // [plane][mt][nt][4]
    load_tiles(0, 0);
    asm volatile("cp.async.commit_group;");
    int buf = 0;

    for (int kc = 0; kc < 8; ++kc) {
        asm volatile("cp.async.wait_group 0;");
        __syncthreads();
        if (kc < 7) {
            load_tiles((kc + 1) * 64, buf ^ 1);
            asm volatile("cp.async.commit_group;");
        }
        const int k0 = kc * 64;
#pragma unroll
        for (int ks = 0; ks < 4; ++ks) {
            uint32_t a[2][4];
#pragma unroll
            for (int mt = 0; mt < 2; ++mt) {
                uint32_t addr = aBase + (uint32_t)(buf * ASTG + (mt * 16 * PA + ks * 16) * 2);
                asm volatile(
                    "ldmatrix.sync.aligned.m8n8.x4.shared.b16 {%0,%1,%2,%3}, [%4];"
                    : "=r"(a[mt][0]), "=r"(a[mt][1]), "=r"(a[mt][2]), "=r"(a[mt][3])
                    : "r"(addr));
            }
            if (MODE == 1) {
                int kb = (k0 >> 1) + ks * 8 + (lane & 3);
                uint32_t kl = *(const uint32_t*)&kvp[kb];
                uint32_t kh = *(const uint32_t*)&kvp[kb + 4];
#pragma unroll
                for (int mt = 0; mt < 2; ++mt) {
                    hmul2u(a[mt][0], kl);
                    hmul2u(a[mt][1], kl);
                    hmul2u(a[mt][2], kh);
                    hmul2u(a[mt][3], kh);
                }
            }
#pragma unroll
            for (int plane = 0; plane < NPLANES; ++plane) {
                uint32_t b[4][2];
#pragma unroll
                for (int ntp = 0; ntp < 2; ++ntp) {   // 2 n8-groups per x4.trans
                    uint32_t addr = bBase4 + (uint32_t)(buf * BSTG +
                        ((plane * 64 + ks * 16) * PB + ntp * 16) * 2);
                    asm volatile(
                        "ldmatrix.sync.aligned.m8n8.x4.trans.shared.b16 {%0,%1,%2,%3}, [%4];"
                        : "=r"(b[2 * ntp][0]), "=r"(b[2 * ntp][1]),
                          "=r"(b[2 * ntp + 1][0]), "=r"(b[2 * ntp + 1][1])
                        : "r"(addr));
                }
#pragma unroll
                for (int mt = 0; mt < 2; ++mt)
#pragma unroll
                    for (int nt = 0; nt < 4; ++nt)
                        mma16816(acc[plane][mt][nt], a[mt], b[nt]);
            }
        }
        buf ^= 1;
    }

    // ---- epilogue ----
#pragma unroll
    for (int mt = 0; mt < 2; ++mt) {
#pragma unroll
        for (int nt = 0; nt < 4; ++nt) {
#pragma unroll
            for (int half = 0; half < 2; ++half) {
                int row = m0 + wm * 32 + mt * 16 + (lane >> 2) + half * 8;
                int col0 = wn * 32 + nt * 8 + (lane & 3) * 2;
                float c0, c1;
                if (MODE == 0) {
                    c0 = fmaf(acc[NPLANES - 1][mt][nt][half * 2 + 0], 0x1p-12f,
                              acc[0][mt][nt][half * 2 + 0]);
                    c1 = fmaf(acc[NPLANES - 1][mt][nt][half * 2 + 1], 0x1p-12f,
                              acc[0][mt][nt][half * 2 + 1]);
                } else {
                    c0 = acc[0][mt][nt][half * 2 + 0];
                    c1 = acc[0][mt][nt][half * 2 + 1];
                }
                if (MODE == 0) {
                    int lc = nl0 + col0;
                    float b0 = 0.f, b1 = 0.f;
                    if (wsel == 0) { b0 = bq[lc]; b1 = bq[lc + 1]; }
                    else if (wsel == 1) { b0 = bk[lc]; b1 = bk[lc + 1]; }
                    *(float2*)&g_y[(size_t)row * QC_ + n0 + col0] =
                        make_float2(c0 + b0, c1 + b1);
                } else {
                    int c = n0 + col0;
                    float2 o;
#pragma unroll
                    for (int e = 0; e < 2; ++e) {
                        int cc = c + e;
                        float gamma = bnp[cc], beta = bnp[512 + cc];
                        float mean = bnp[1024 + cc], var = bnp[1536 + cc];
                        float rinv = 1.0f / sqrtf(var + 1e-5f);
                        float yv = (e == 0 ? c0 : c1) + bp[cc];
                        float u = __fadd_rn(__fmul_rn(__fmul_rn(gamma, __fadd_rn(yv, -mean)), rinv), beta);
                        float r = u + x[(size_t)row * C_ + cc];
                        if (e == 0) o.x = r; else o.y = r;
                    }
                    *(float2*)&outp[(size_t)row * C_ + c] = o;
                }
            }
        }
    }
}

// ---------------------------------------------------------------------------
// 3) BN + LIF for q,k,v — 4x vectorized; v spikes also scattered into d_out
// ---------------------------------------------------------------------------
__global__ void bn_lif_kernel(const float* __restrict__ bnq,
                              const float* __restrict__ bnk,
                              const float* __restrict__ bnv,
                              float* __restrict__ vout) {
    size_t idx = (size_t)blockIdx.x * blockDim.x + threadIdx.x;
    int sel = (int)(idx / (BNC_ / 4));
    int r4 = (int)(idx % (BNC_ / 4));
    int r = r4 * 4;
    int c = r & 511;
    int bn_i = r >> 9;
    const float* p = (sel == 0) ? bnq : (sel == 1) ? bnk : bnv;
    float4 gamma = *(const float4*)&p[c];
    float4 beta  = *(const float4*)&p[512 + c];
    float4 mean  = *(const float4*)&p[1024 + c];
    float4 var   = *(const float4*)&p[1536 + c];
    float ri0 = 1.0f / sqrtf(var.x + 1e-5f);
    float ri1 = 1.0f / sqrtf(var.y + 1e-5f);
    float ri2 = 1.0f / sqrtf(var.z + 1e-5f);
    float ri3 = 1.0f / sqrtf(var.w + 1e-5f);
    __half* dst = (sel == 0) ? g_q : (sel == 1) ? g_k : g_v;
    int colbase = sel * 512 + c;
    float v0 = 0.f, v1 = 0.f, v2 = 0.f, v3 = 0.f;
#pragma unroll
    for (int t = 0; t < T_; ++t) {
        float4 y = *(const float4*)&g_y[(size_t)(t * RPT_ + bn_i) * QC_ + colbase];
        float u0 = __fadd_rn(__fmul_rn(__fmul_rn(gamma.x, __fadd_rn(y.x, -mean.x)), ri0), beta.x);
        float u1 = __fadd_rn(__fmul_rn(__fmul_rn(gamma.y, __fadd_rn(y.y, -mean.y)), ri1), beta.y);
        float u2 = __fadd_rn(__fmul_rn(__fmul_rn(gamma.z, __fadd_rn(y.z, -mean.z)), ri2), beta.z);
        float u3 = __fadd_rn(__fmul_rn(__fmul_rn(gamma.w, __fadd_rn(y.w, -mean.w)), ri3), beta.w);
        v0 = v0 + (u0 - v0) * 0.5f;
        v1 = v1 + (u1 - v1) * 0.5f;
        v2 = v2 + (u2 - v2) * 0.5f;
        v3 = v3 + (u3 - v3) * 0.5f;
        bool s0 = v0 >= 1.f, s1 = v1 >= 1.f, s2 = v2 >= 1.f, s3 = v3 >= 1.f;
        float f0 = s0 ? 1.f : 0.f, f1 = s1 ? 1.f : 0.f;
        float f2 = s2 ? 1.f : 0.f, f3 = s3 ? 1.f : 0.f;
        __half2 lo = __floats2half2_rn(f0, f1);
        __half2 hi = __floats2half2_rn(f2, f3);
        uint2 pk;
        pk.x = *(uint32_t*)&lo;
        pk.y = *(uint32_t*)&hi;
        *(uint2*)&dst[(size_t)t * BNC_ + r] = pk;
        if (sel == 2) {
            int b = bn_i >> 10, n = bn_i & 1023, h = c >> 6, d = c & 63;
            *(float4*)&vout[((((size_t)t * B_ + b) * H_ + h) * NN_ + n) * D_ + d] =
                make_float4(f0, f1, f2, f3);
        }
        if (s0) v0 = 0.f;
        if (s1) v1 = 0.f;
        if (s2) v2 = 0.f;
        if (s3) v3 = 0.f;
    }
}

// ---------------------------------------------------------------------------
// 4) kv = sum_n k*v (exact binary sums), half2-vectorized; then LIF(0.5)
// ---------------------------------------------------------------------------
__global__ void kv_partial_kernel() {
    int blk = blockIdx.x;
    int chunk = blk & 7;
    int tb = blk >> 3;
    int c2 = threadIdx.x;
    const __half2* k2 = (const __half2*)&g_k[(size_t)tb * NN_ * C_ + (size_t)chunk * 128 * C_];
    const __half2* v2 = (const __half2*)&g_v[(size_t)tb * NN_ * C_ + (size_t)chunk * 128 * C_];
    float sx = 0.f, sy = 0.f;
    for (int n = 0; n < 128; ++n) {
        __half2 p = __hmul2(k2[n * 256 + c2], v2[n * 256 + c2]);
        float2 pf = __half22float2(p);
        sx += pf.x;
        sy += pf.y;
    }
    g_kvpart[(size_t)blk * C_ + 2 * c2]     = sx;
    g_kvpart[(size_t)blk * C_ + 2 * c2 + 1] = sy;
}

__global__ void kv_lif_kernel() {
    int idx = blockIdx.x * blockDim.x + threadIdx.x;
    int b = idx >> 9, c = idx & 511;
    float v = 0.f;
#pragma unroll
    for (int t = 0; t < T_; ++t) {
        int tb = t * B_ + b;
        float s = 0.f;
#pragma unroll
        for (int ch = 0; ch < 8; ++ch)
            s += g_kvpart[((size_t)tb * 8 + ch) * C_ + c];
        v = v + (s - v) * 0.5f;
        bool sp = (v >= 0.5f);
        g_kvs[(size_t)tb * C_ + c] = sp ? __float2half(1.f) : __float2half(0.f);
        if (sp) v = 0.f;
    }
}

// ---------------------------------------------------------------------------
extern "C" void kernel_launch(void* const* d_in, const int* in_sizes, int n_in,
                              void* d_out, int out_size) {
    const float* x   = (const float*)d_in[0];
    const float* Wq  = (const float*)d_in[1];
    const float* bq  = (const float*)d_in[2];
    const float* Wk  = (const float*)d_in[3];
    const float* bk  = (const float*)d_in[4];
    const float* Wv  = (const float*)d_in[5];
    const float* Wp  = (const float*)d_in[6];
    const float* bp  = (const float*)d_in[7];
    const float* bnq = (const float*)d_in[8];
    const float* bnk = (const float*)d_in[9];
    const float* bnv = (const float*)d_in[10];
    const float* bnp = (const float*)d_in[11];
    float* out  = (float*)d_out;
    float* vout = out + (size_t)M_ * C_;   // tuple output: (out, v) concatenated

    cudaFuncSetAttribute((const void*)gemm_tc_kernel<0>,
                         cudaFuncAttributeMaxDynamicSharedMemorySize, SM_TOTAL);
    cudaFuncSetAttribute((const void*)gemm_tc_kernel<1>,
                         cudaFuncAttributeMaxDynamicSharedMemorySize, SM_TOTAL);

    prep_split_kernel<<<4096, 256>>>(Wq, Wk, Wv, Wp);
    lif_x_kernel<<<BNC_ / 4 / 256, 256>>>(x);

    dim3 gq(M_ / 128, QC_ / 64);   // (512, 24)
    gemm_tc_kernel<0><<<gq, 256, SM_TOTAL>>>(bq, bk, nullptr, nullptr, nullptr, nullptr);

    bn_lif_kernel<<<(3 * BNC_ / 4) / 256, 256>>>(bnq, bnk, bnv, vout);

    kv_partial_kernel<<<T_ * B_ * 8, 256>>>();
    kv_lif_kernel<<<(B_ * C_) / 256, 256>>>();

    dim3 gp(M_ / 128, C_ / 64);    // (512, 8)
    gemm_tc_kernel<1><<<gp, 256, SM_TOTAL>>>(nullptr, nullptr, bp, bnp, x, out);
}

// round 17
// speedup vs baseline: 1.1365x; 1.0182x over previous
#include <cuda_runtime.h>
#include <cuda_fp16.h>
#include <math.h>
#include <stdint.h>

// Problem dims
#define T_   4
#define B_   16
#define NN_  1024
#define C_   512
#define H_   8
#define D_   64
#define M_   65536        // T*B*N
#define BNC_ 8388608      // B*N*C
#define RPT_ 16384        // rows per T step (B*N)
#define QC_  1536         // fused QKV output columns

// Scratch (device globals; no allocation allowed)
__device__ __half g_xs[(size_t)M_ * C_];
__device__ float  g_y [(size_t)M_ * QC_];
__device__ __half g_q [(size_t)M_ * C_];
__device__ __half g_kvs[(size_t)T_ * B_ * C_];
// Split weights: 4 matrices x hi/mid fp16 planes (mid scaled by 2^12)
__device__ __half g_Wh[4 * C_ * C_];
__device__ __half g_Wm[4 * C_ * C_];

// ---------------------------------------------------------------------------
// 0) split weights: w = hi + mid*2^-12, both fp16 (residual <= 2^-24 |w|)
// ---------------------------------------------------------------------------
__global__ void prep_split_kernel(const float* __restrict__ Wq,
                                  const float* __restrict__ Wk,
                                  const float* __restrict__ Wv,
                                  const float* __restrict__ Wp) {
    int i = blockIdx.x * blockDim.x + threadIdx.x;
    int mat = i >> 18;
    int r = i & 262143;
    const float* src = (mat == 0) ? Wq : (mat == 1) ? Wk : (mat == 2) ? Wv : Wp;
    float w = src[r];
    __half h = __float2half_rn(w);
    float r1 = w - __half2float(h);
    g_Wh[i] = h;
    g_Wm[i] = __float2half_rn(r1 * 4096.0f);   // scaled into normal range
}

// ---------------------------------------------------------------------------
// 1) shortcut LIF on x -> binary xs (fp16), float4-vectorized
// ---------------------------------------------------------------------------
__global__ void lif_x_kernel(const float* __restrict__ x) {
    size_t i4 = (size_t)blockIdx.x * blockDim.x + threadIdx.x;
    const float4* x4 = (const float4*)x;
    uint2* dst = (uint2*)g_xs;
    float v0 = 0.f, v1 = 0.f, v2 = 0.f, v3 = 0.f;
#pragma unroll
    for (int t = 0; t < T_; ++t) {
        float4 xv = x4[(size_t)t * (BNC_ / 4) + i4];
        v0 = v0 + (xv.x - v0) * 0.5f;
        v1 = v1 + (xv.y - v1) * 0.5f;
        v2 = v2 + (xv.z - v2) * 0.5f;
        v3 = v3 + (xv.w - v3) * 0.5f;
        bool s0 = v0 >= 1.f, s1 = v1 >= 1.f, s2 = v2 >= 1.f, s3 = v3 >= 1.f;
        __half2 lo = __floats2half2_rn(s0 ? 1.f : 0.f, s1 ? 1.f : 0.f);
        __half2 hi = __floats2half2_rn(s2 ? 1.f : 0.f, s3 ? 1.f : 0.f);
        uint2 o;
        o.x = *(uint32_t*)&lo;
        o.y = *(uint32_t*)&hi;
        dst[(size_t)t * (BNC_ / 4) + i4] = o;
        if (s0) v0 = 0.f;
        if (s1) v1 = 0.f;
        if (s2) v2 = 0.f;
        if (s3) v3 = 0.f;
    }
}

// ---------------------------------------------------------------------------
// Tensor-core GEMM: CTA 128x64, BK=64 (8 chunks), 2-stage cp.async ring.
// B fragments via ldmatrix.x4.trans.
// MODE 0 (QKV): fp16 2-plane weights, per-plane fp32 acc, fold hi + 2^-12*mid.
// MODE 1 (P):   fp16 hi plane only; kv mask on A fragments; epi bias+BN+identity.
// ---------------------------------------------------------------------------
#define PA 72   // A smem pitch (fp16); 144B rows, conflict-free
#define PB 72   // B smem pitch; 144B
#define ASTG (128 * PA * 2)          // 18432 B per A stage
#define BSTG (2 * 64 * PB * 2)       // 18432 B per B stage
#define SM_TOTAL (2 * (ASTG + BSTG)) // 73728 B dynamic smem

__device__ __forceinline__ uint32_t smem_u32(const void* p) {
    uint32_t a;
    asm("{ .reg .u64 t; cvta.to.shared.u64 t, %1; cvt.u32.u64 %0, t; }" : "=r"(a) : "l"(p));
    return a;
}
__device__ __forceinline__ void mma16816(float* c, const uint32_t* a, const uint32_t* b) {
    asm volatile(
        "mma.sync.aligned.m16n8k16.row.col.f32.f16.f16.f32 "
        "{%0,%1,%2,%3}, {%4,%5,%6,%7}, {%8,%9}, {%0,%1,%2,%3};"
        : "+f"(c[0]), "+f"(c[1]), "+f"(c[2]), "+f"(c[3])
        : "r"(a[0]), "r"(a[1]), "r"(a[2]), "r"(a[3]), "r"(b[0]), "r"(b[1]));
}
__device__ __forceinline__ void cpasync16(uint32_t dst, const void* src) {
    asm volatile("cp.async.cg.shared.global [%0], [%1], 16;" :: "r"(dst), "l"(src));
}
__device__ __forceinline__ void hmul2u(uint32_t& r, uint32_t m) {
    __half2 t = __hmul2(*(__half2*)&r, *(__half2*)&m);
    r = *(uint32_t*)&t;
}

template <int MODE>
__global__ void __launch_bounds__(256, 2)
gemm_tc_kernel(const float* __restrict__ bq,
               const float* __restrict__ bk,
               const float* __restrict__ bp,
               const float* __restrict__ bnp,
               const float* __restrict__ x,
               float* __restrict__ outp) {
    extern __shared__ __align__(16) char dynsmem[];
    const uint32_t sAs = smem_u32(dynsmem);
    const uint32_t sBs = sAs + 2 * ASTG;

    constexpr int NPLANES = (MODE == 0) ? 2 : 1;

    const int m0 = blockIdx.x * 128;
    const int n0 = blockIdx.y * 64;
    const int wsel = (MODE == 0) ? (n0 >> 9) : 3;
    const int nl0 = (MODE == 0) ? (n0 & 511) : n0;
    const __half* Wh = &g_Wh[(size_t)wsel * C_ * C_];
    const __half* Wm = &g_Wm[(size_t)wsel * C_ * C_];

    const int tid = threadIdx.x;
    const int lane = tid & 31;
    const int warp = tid >> 5;
    const int wm = warp & 3;
    const int wn = warp >> 2;

    const uint32_t aBase = sAs + (uint32_t)(((wm * 32 + (lane & 15)) * PA + (lane >> 4) * 8) * 2);
    const uint32_t bBase4 = sBs + (uint32_t)((
        (((lane >> 3) & 1) * 8 + (lane & 7)) * PB +
        wn * 32 + (lane >> 4) * 8) * 2);

    const __half* Abase = (MODE == 0) ? &g_xs[(size_t)m0 * C_]
                                      : &g_q[(size_t)m0 * C_];
    const int tb = m0 >> 10;
    const __half2* kvp = (const __half2*)&g_kvs[(size_t)tb * C_];

    auto load_tiles = [&](int k0, int stg) {
#pragma unroll
        for (int i = 0; i < 4; ++i) {
            int idx = i * 256 + tid;
            int row = idx >> 3;
            int kc8 = (idx & 7) * 8;
            uint32_t dst = sAs + (uint32_t)(stg * ASTG + (row * PA + kc8) * 2);
            cpasync16(dst, Abase + (size_t)row * C_ + k0 + kc8);
        }
#pragma unroll
        for (int j = 0; j < 2 * NPLANES; ++j) {
            int idx = j * 256 + tid;
            int plane = idx >> 9;
            int rem = idx & 511;
            int kr = rem >> 3;
            int nc = (rem & 7) * 8;
            const __half* src = (plane == 0) ? Wh : Wm;
            uint32_t dst = sBs + (uint32_t)(stg * BSTG + ((plane * 64 + kr) * PB + nc) * 2);
            cpasync16(dst, src + (size_t)(k0 + kr) * C_ + nl0 + nc);
        }
    };

    float acc[NPLANES][2][4][4] = {};
    load_tiles(0, 0);
    asm volatile("cp.async.commit_group;");
    int buf = 0;

    for (int kc = 0; kc < 8; ++kc) {
        asm volatile("cp.async.wait_group 0;");
        __syncthreads();
        if (kc < 7) {
            load_tiles((kc + 1) * 64, buf ^ 1);
            asm volatile("cp.async.commit_group;");
        }
        const int k0 = kc * 64;
#pragma unroll
        for (int ks = 0; ks < 4; ++ks) {
            uint32_t a[2][4];
#pragma unroll
            for (int mt = 0; mt < 2; ++mt) {
                uint32_t addr = aBase + (uint32_t)(buf * ASTG + (mt * 16 * PA + ks * 16) * 2);
                asm volatile(
                    "ldmatrix.sync.aligned.m8n8.x4.shared.b16 {%0,%1,%2,%3}, [%4];"
                    : "=r"(a[mt][0]), "=r"(a[mt][1]), "=r"(a[mt][2]), "=r"(a[mt][3])
                    : "r"(addr));
            }
            if (MODE == 1) {
                int kb = (k0 >> 1) + ks * 8 + (lane & 3);
                uint32_t kl = *(const uint32_t*)&kvp[kb];
                uint32_t kh = *(const uint32_t*)&kvp[kb + 4];
#pragma unroll
                for (int mt = 0; mt < 2; ++mt) {
                    hmul2u(a[mt][0], kl);
                    hmul2u(a[mt][1], kl);
                    hmul2u(a[mt][2], kh);
                    hmul2u(a[mt][3], kh);
                }
            }
#pragma unroll
            for (int plane = 0; plane < NPLANES; ++plane) {
                uint32_t b[4][2];
#pragma unroll
                for (int ntp = 0; ntp < 2; ++ntp) {
                    uint32_t addr = bBase4 + (uint32_t)(buf * BSTG +
                        ((plane * 64 + ks * 16) * PB + ntp * 16) * 2);
                    asm volatile(
                        "ldmatrix.sync.aligned.m8n8.x4.trans.shared.b16 {%0,%1,%2,%3}, [%4];"
                        : "=r"(b[2 * ntp][0]), "=r"(b[2 * ntp][1]),
                          "=r"(b[2 * ntp + 1][0]), "=r"(b[2 * ntp + 1][1])
                        : "r"(addr));
                }
#pragma unroll
                for (int mt = 0; mt < 2; ++mt)
#pragma unroll
                    for (int nt = 0; nt < 4; ++nt)
                        mma16816(acc[plane][mt][nt], a[mt], b[nt]);
            }
        }
        buf ^= 1;
    }

    // ---- epilogue ----
#pragma unroll
    for (int mt = 0; mt < 2; ++mt) {
#pragma unroll
        for (int nt = 0; nt < 4; ++nt) {
#pragma unroll
            for (int half = 0; half < 2; ++half) {
                int row = m0 + wm * 32 + mt * 16 + (lane >> 2) + half * 8;
                int col0 = wn * 32 + nt * 8 + (lane & 3) * 2;
                float c0, c1;
                if (MODE == 0) {
                    c0 = fmaf(acc[NPLANES - 1][mt][nt][half * 2 + 0], 0x1p-12f,
                              acc[0][mt][nt][half * 2 + 0]);
                    c1 = fmaf(acc[NPLANES - 1][mt][nt][half * 2 + 1], 0x1p-12f,
                              acc[0][mt][nt][half * 2 + 1]);
                } else {
                    c0 = acc[0][mt][nt][half * 2 + 0];
                    c1 = acc[0][mt][nt][half * 2 + 1];
                }
                if (MODE == 0) {
                    int lc = nl0 + col0;
                    float b0 = 0.f, b1 = 0.f;
                    if (wsel == 0) { b0 = bq[lc]; b1 = bq[lc + 1]; }
                    else if (wsel == 1) { b0 = bk[lc]; b1 = bk[lc + 1]; }
                    *(float2*)&g_y[(size_t)row * QC_ + n0 + col0] =
                        make_float2(c0 + b0, c1 + b1);
                } else {
                    int c = n0 + col0;
                    float2 o;
#pragma unroll
                    for (int e = 0; e < 2; ++e) {
                        int cc = c + e;
                        float gamma = bnp[cc], beta = bnp[512 + cc];
                        float mean = bnp[1024 + cc], var = bnp[1536 + cc];
                        float rinv = 1.0f / sqrtf(var + 1e-5f);
                        float yv = (e == 0 ? c0 : c1) + bp[cc];
                        float u = __fadd_rn(__fmul_rn(__fmul_rn(gamma, __fadd_rn(yv, -mean)), rinv), beta);
                        float r = u + x[(size_t)row * C_ + cc];
                        if (e == 0) o.x = r; else o.y = r;
                    }
                    *(float2*)&outp[(size_t)row * C_ + c] = o;
                }
            }
        }
    }
}

// ---------------------------------------------------------------------------
// 3a) BN + LIF for q only (unchanged arithmetic), 4x vectorized
// ---------------------------------------------------------------------------
__global__ void bn_lif_q_kernel(const float* __restrict__ bnq) {
    size_t idx = (size_t)blockIdx.x * blockDim.x + threadIdx.x;  // BNC_/4
    int r = (int)(idx * 4);
    int c = r & 511;
    int bn_i = r >> 9;
    float4 gamma = *(const float4*)&bnq[c];
    float4 beta  = *(const float4*)&bnq[512 + c];
    float4 mean  = *(const float4*)&bnq[1024 + c];
    float4 var   = *(const float4*)&bnq[1536 + c];
    float ri0 = 1.0f / sqrtf(var.x + 1e-5f);
    float ri1 = 1.0f / sqrtf(var.y + 1e-5f);
    float ri2 = 1.0f / sqrtf(var.z + 1e-5f);
    float ri3 = 1.0f / sqrtf(var.w + 1e-5f);
    float v0 = 0.f, v1 = 0.f, v2 = 0.f, v3 = 0.f;
#pragma unroll
    for (int t = 0; t < T_; ++t) {
        float4 y = *(const float4*)&g_y[(size_t)(t * RPT_ + bn_i) * QC_ + c];
        float u0 = __fadd_rn(__fmul_rn(__fmul_rn(gamma.x, __fadd_rn(y.x, -mean.x)), ri0), beta.x);
        float u1 = __fadd_rn(__fmul_rn(__fmul_rn(gamma.y, __fadd_rn(y.y, -mean.y)), ri1), beta.y);
        float u2 = __fadd_rn(__fmul_rn(__fmul_rn(gamma.z, __fadd_rn(y.z, -mean.z)), ri2), beta.z);
        float u3 = __fadd_rn(__fmul_rn(__fmul_rn(gamma.w, __fadd_rn(y.w, -mean.w)), ri3), beta.w);
        v0 = v0 + (u0 - v0) * 0.5f;
        v1 = v1 + (u1 - v1) * 0.5f;
        v2 = v2 + (u2 - v2) * 0.5f;
        v3 = v3 + (u3 - v3) * 0.5f;
        bool s0 = v0 >= 1.f, s1 = v1 >= 1.f, s2 = v2 >= 1.f, s3 = v3 >= 1.f;
        __half2 lo = __floats2half2_rn(s0 ? 1.f : 0.f, s1 ? 1.f : 0.f);
        __half2 hi = __floats2half2_rn(s2 ? 1.f : 0.f, s3 ? 1.f : 0.f);
        uint2 pk;
        pk.x = *(uint32_t*)&lo;
        pk.y = *(uint32_t*)&hi;
        *(uint2*)&g_q[(size_t)t * BNC_ + r] = pk;
        if (s0) v0 = 0.f;
        if (s1) v1 = 0.f;
        if (s2) v2 = 0.f;
        if (s3) v3 = 0.f;
    }
}

// ---------------------------------------------------------------------------
// 3b) FUSED: BN+LIF for k,v + vout scatter + kv = sum_n k*v + kv-LIF(0.5).
// grid = 16 b x 16 c-chunks (32 ch each); block 256 = 8 ch-threads x 32 n-grps.
// Per-thread: k & v LIF scans for its (b, n-slice, 4 ch), exact integer k*v
// accumulation; smem reduce over n-groups; inline kv LIF writes g_kvs.
// ---------------------------------------------------------------------------
__global__ void __launch_bounds__(256)
bn_lif_kv_kernel(const float* __restrict__ bnk,
                 const float* __restrict__ bnv,
                 float* __restrict__ vout) {
    __shared__ float red[32][4][32];   // [ngroup][t][local ch] 16 KB
    const int blk = blockIdx.x;        // 0..255
    const int b = blk >> 4;
    const int cch = blk & 15;          // 32-channel chunk
    const int tid = threadIdx.x;
    const int tc = tid & 7;            // 8 ch-threads x 4 ch
    const int ng = tid >> 3;           // 0..31 n-groups x 32 n
    const int c = cch * 32 + tc * 4;

    float4 gk = *(const float4*)&bnk[c];
    float4 bk_ = *(const float4*)&bnk[512 + c];
    float4 mk = *(const float4*)&bnk[1024 + c];
    float4 vk = *(const float4*)&bnk[1536 + c];
    float rk0 = 1.0f / sqrtf(vk.x + 1e-5f);
    float rk1 = 1.0f / sqrtf(vk.y + 1e-5f);
    float rk2 = 1.0f / sqrtf(vk.z + 1e-5f);
    float rk3 = 1.0f / sqrtf(vk.w + 1e-5f);
    float4 gv = *(const float4*)&bnv[c];
    float4 bv_ = *(const float4*)&bnv[512 + c];
    float4 mv = *(const float4*)&bnv[1024 + c];
    float4 vv = *(const float4*)&bnv[1536 + c];
    float rv0 = 1.0f / sqrtf(vv.x + 1e-5f);
    float rv1 = 1.0f / sqrtf(vv.y + 1e-5f);
    float rv2 = 1.0f / sqrtf(vv.z + 1e-5f);
    float rv3 = 1.0f / sqrtf(vv.w + 1e-5f);

    const int h = c >> 6, d = c & 63;
    float kvacc[4][4] = {};

    for (int nn = 0; nn < 32; ++nn) {
        int n = ng * 32 + nn;
        int bn_i = b * 1024 + n;
        float ks0 = 0.f, ks1 = 0.f, ks2 = 0.f, ks3 = 0.f;
        float vs0 = 0.f, vs1 = 0.f, vs2 = 0.f, vs3 = 0.f;
#pragma unroll
        for (int t = 0; t < T_; ++t) {
            const float* rowy = &g_y[(size_t)(t * RPT_ + bn_i) * QC_];
            float4 yk = *(const float4*)&rowy[512 + c];
            float4 yv = *(const float4*)&rowy[1024 + c];
            float uk0 = __fadd_rn(__fmul_rn(__fmul_rn(gk.x, __fadd_rn(yk.x, -mk.x)), rk0), bk_.x);
            float uk1 = __fadd_rn(__fmul_rn(__fmul_rn(gk.y, __fadd_rn(yk.y, -mk.y)), rk1), bk_.y);
            float uk2 = __fadd_rn(__fmul_rn(__fmul_rn(gk.z, __fadd_rn(yk.z, -mk.z)), rk2), bk_.z);
            float uk3 = __fadd_rn(__fmul_rn(__fmul_rn(gk.w, __fadd_rn(yk.w, -mk.w)), rk3), bk_.w);
            float uv0 = __fadd_rn(__fmul_rn(__fmul_rn(gv.x, __fadd_rn(yv.x, -mv.x)), rv0), bv_.x);
            float uv1 = __fadd_rn(__fmul_rn(__fmul_rn(gv.y, __fadd_rn(yv.y, -mv.y)), rv1), bv_.y);
            float uv2 = __fadd_rn(__fmul_rn(__fmul_rn(gv.z, __fadd_rn(yv.z, -mv.z)), rv2), bv_.z);
            float uv3 = __fadd_rn(__fmul_rn(__fmul_rn(gv.w, __fadd_rn(yv.w, -mv.w)), rv3), bv_.w);
            ks0 = ks0 + (uk0 - ks0) * 0.5f;
            ks1 = ks1 + (uk1 - ks1) * 0.5f;
            ks2 = ks2 + (uk2 - ks2) * 0.5f;
            ks3 = ks3 + (uk3 - ks3) * 0.5f;
            vs0 = vs0 + (uv0 - vs0) * 0.5f;
            vs1 = vs1 + (uv1 - vs1) * 0.5f;
            vs2 = vs2 + (uv2 - vs2) * 0.5f;
            vs3 = vs3 + (uv3 - vs3) * 0.5f;
            bool k0s = ks0 >= 1.f, k1s = ks1 >= 1.f, k2s = ks2 >= 1.f, k3s = ks3 >= 1.f;
            bool v0s = vs0 >= 1.f, v1s = vs1 >= 1.f, v2s = vs2 >= 1.f, v3s = vs3 >= 1.f;
            float f0 = v0s ? 1.f : 0.f, f1 = v1s ? 1.f : 0.f;
            float f2 = v2s ? 1.f : 0.f, f3 = v3s ? 1.f : 0.f;
            *(float4*)&vout[((((size_t)t * B_ + b) * H_ + h) * NN_ + n) * D_ + d] =
                make_float4(f0, f1, f2, f3);
            if (k0s && v0s) kvacc[t][0] += 1.f;
            if (k1s && v1s) kvacc[t][1] += 1.f;
            if (k2s && v2s) kvacc[t][2] += 1.f;
            if (k3s && v3s) kvacc[t][3] += 1.f;
            if (k0s) ks0 = 0.f;
            if (k1s) ks1 = 0.f;
            if (k2s) ks2 = 0.f;
            if (k3s) ks3 = 0.f;
            if (v0s) vs0 = 0.f;
            if (v1s) vs1 = 0.f;
            if (v2s) vs2 = 0.f;
            if (v3s) vs3 = 0.f;
        }
    }
#pragma unroll
    for (int t = 0; t < T_; ++t)
#pragma unroll
        for (int e = 0; e < 4; ++e)
            red[ng][t][tc * 4 + e] = kvacc[t][e];
    __syncthreads();

    if (tid < 32) {
        int chl = tid;                 // local channel 0..31
        float s[4];
#pragma unroll
        for (int t = 0; t < T_; ++t) {
            float acc = 0.f;
#pragma unroll
            for (int g = 0; g < 32; ++g) acc += red[g][t][chl];
            s[t] = acc;
        }
        float v = 0.f;
#pragma unroll
        for (int t = 0; t < T_; ++t) {
            v = v + (s[t] - v) * 0.5f;
            bool sp = (v >= 0.5f);
            g_kvs[(size_t)(t * B_ + b) * C_ + cch * 32 + chl] =
                sp ? __float2half(1.f) : __float2half(0.f);
            if (sp) v = 0.f;
        }
    }
}

// ---------------------------------------------------------------------------
extern "C" void kernel_launch(void* const* d_in, const int* in_sizes, int n_in,
                              void* d_out, int out_size) {
    const float* x   = (const float*)d_in[0];
    const float* Wq  = (const float*)d_in[1];
    const float* bq  = (const float*)d_in[2];
    const float* Wk  = (const float*)d_in[3];
    const float* bk  = (const float*)d_in[4];
    const float* Wv  = (const float*)d_in[5];
    const float* Wp  = (const float*)d_in[6];
    const float* bp  = (const float*)d_in[7];
    const float* bnq = (const float*)d_in[8];
    const float* bnk = (const float*)d_in[9];
    const float* bnv = (const float*)d_in[10];
    const float* bnp = (const float*)d_in[11];
    float* out  = (float*)d_out;
    float* vout = out + (size_t)M_ * C_;   // tuple output: (out, v) concatenated

    cudaFuncSetAttribute((const void*)gemm_tc_kernel<0>,
                         cudaFuncAttributeMaxDynamicSharedMemorySize, SM_TOTAL);
    cudaFuncSetAttribute((const void*)gemm_tc_kernel<1>,
                         cudaFuncAttributeMaxDynamicSharedMemorySize, SM_TOTAL);

    prep_split_kernel<<<4096, 256>>>(Wq, Wk, Wv, Wp);
    lif_x_kernel<<<BNC_ / 4 / 256, 256>>>(x);

    dim3 gq(M_ / 128, QC_ / 64);   // (512, 24)
    gemm_tc_kernel<0><<<gq, 256, SM_TOTAL>>>(bq, bk, nullptr, nullptr, nullptr, nullptr);

    bn_lif_q_kernel<<<(BNC_ / 4) / 256, 256>>>(bnq);
    bn_lif_kv_kernel<<<256, 256>>>(bnk, bnv, vout);

    dim3 gp(M_ / 128, C_ / 64);    // (512, 8)
    gemm_tc_kernel<1><<<gp, 256, SM_TOTAL>>>(nullptr, nullptr, bp, bnp, x, out);
}